// round 6
// baseline (speedup 1.0000x reference)
#include <cuda_runtime.h>
#include <cstdint>
#include <cstddef>

#define BB   128
#define SEQ  720
#define PRED 336
#define ENC  321
#define DD   512
#define NG   2048           // 4*D
#define XSTR (SEQ*ENC)
#define KXP  328            // ENC padded to 41*8
#define EPAD 384            // ENC padded for W_pred^T tiles
#define NBLK 128            // persistent grid

// -------- persistent device scratch --------
__device__ float g_WX  [KXP * NG];        // Wih^T gate-interleaved [k][n], n=d*4+gate
__device__ float g_WE  [DD * NG];         // Whh^T gate-interleaved
__device__ float g_WD  [DD * NG];         // decoder (Wih@Wp + Whh)^T gate-interleaved
__device__ float g_WpT2[DD * EPAD];       // W_pred^T padded [k][e]
__device__ float g_bias [NG];
__device__ float g_biasd[NG];
__device__ float g_h[2][BB * DD];                     // ping-pong hidden state
__device__ float g_xg[(size_t)SEQ * BB * NG];         // precomputed x projections
__device__ float g_hist[(size_t)PRED * BB * DD];      // decoder h_t log

__device__ volatile unsigned g_bar_gen;
__device__ unsigned g_bar_cnt;

// -------- packed fp32x2 FMA --------
__device__ __forceinline__ void fma2(float2 &d, float2 a, float2 b) {
    unsigned long long &du = reinterpret_cast<unsigned long long &>(d);
    unsigned long long au  = reinterpret_cast<unsigned long long &>(a);
    unsigned long long bu  = reinterpret_cast<unsigned long long &>(b);
    asm("fma.rn.f32x2 %0, %1, %2, %0;" : "+l"(du) : "l"(au), "l"(bu));
}

__device__ __forceinline__ float sigm(float x) { return 1.f / (1.f + __expf(-x)); }

// -------- grid barrier (one per step) --------
__device__ __forceinline__ void grid_sync() {
    __syncthreads();
    if (threadIdx.x == 0) {
        __threadfence();
        unsigned gen = g_bar_gen;
        if (atomicAdd(&g_bar_cnt, 1u) == NBLK - 1) {
            g_bar_cnt = 0;
            __threadfence();
            g_bar_gen = gen + 1;
        } else {
            int sp = 0;
            while (g_bar_gen == gen) { if (++sp > 100) __nanosleep(40); }
        }
        __threadfence();
    }
    __syncthreads();
}

// -------- GEMM micro-kernel pieces (xg_proj / final_pred) --------
struct Slots { int klp[4], mmp[4], kwp[4], nlp[4]; };

__device__ __forceinline__ void make_slots(Slots &s, int tid) {
#pragma unroll
    for (int p = 0; p < 4; ++p) {
        int lin = tid + p * 256;
        s.klp[p] = lin & 7;   s.mmp[p] = lin >> 3;
        s.nlp[p] = lin & 127; s.kwp[p] = lin >> 7;
    }
}

__device__ __forceinline__ void stage(const Slots &s, const float *ur, const float *wr,
                                      float *U, float *W) {
#pragma unroll
    for (int p = 0; p < 4; ++p) {
        U[s.klp[p] * 132 + s.mmp[p]] = ur[p];
        W[s.kwp[p] * 128 + s.nlp[p]] = wr[p];
    }
}

__device__ __forceinline__ void mma8(float2 acc[8][4], const float *U, const float *W,
                                     int tm8, int tn8) {
#pragma unroll
    for (int q = 0; q < 8; ++q) {
        const float4 a0 = *(const float4 *)&U[q * 132 + tm8];
        const float4 a1 = *(const float4 *)&U[q * 132 + tm8 + 4];
        const float4 b0 = *(const float4 *)&W[q * 128 + tn8];
        const float4 b1 = *(const float4 *)&W[q * 128 + tn8 + 4];
        float  av[8] = {a0.x, a0.y, a0.z, a0.w, a1.x, a1.y, a1.z, a1.w};
        float2 bv[4] = {make_float2(b0.x, b0.y), make_float2(b0.z, b0.w),
                        make_float2(b1.x, b1.y), make_float2(b1.z, b1.w)};
#pragma unroll
        for (int r = 0; r < 8; ++r) {
            float2 ad = make_float2(av[r], av[r]);
#pragma unroll
            for (int c = 0; c < 4; ++c) fma2(acc[r][c], ad, bv[c]);
        }
    }
}

// ==================== prep kernels ====================
__global__ void prepA(const float *__restrict__ Wih, const float *__restrict__ Whh,
                      const float *__restrict__ bih, const float *__restrict__ bhh,
                      const float *__restrict__ Wp)
{
    int idx = blockIdx.x * 256 + threadIdx.x;
    if (idx < KXP * NG) {
        int k = idx / NG, n = idx - k * NG, d = n >> 2, gate = n & 3, j = gate * DD + d;
        g_WX[idx] = (k < ENC) ? Wih[(size_t)j * ENC + k] : 0.f;
    }
    if (idx < DD * NG) {
        int k = idx / NG, n = idx - k * NG, d = n >> 2, gate = n & 3, j = gate * DD + d;
        g_WE[idx] = Whh[(size_t)j * DD + k];
    }
    if (idx < DD * EPAD) {
        int k = idx / EPAD, e = idx - k * EPAD;
        g_WpT2[idx] = (e < ENC) ? Wp[(size_t)e * DD + k] : 0.f;
    }
    if (idx < NG) {
        int j = idx, n = (j & 511) * 4 + (j >> 9);
        g_bias[n] = bih[j] + bhh[j];
    }
    if (idx < 2 * BB * DD) ((float *)g_h)[idx] = 0.f;
}

// g_WD[k][n] = sum_e Wih[j][e]*Wp[e][k] + Whh[j][k];  biasd[n] = bias[n] + Wih[j]·bp
__global__ void prepB(const float *__restrict__ Wih, const float *__restrict__ Whh,
                      const float *__restrict__ bp)
{
    __shared__ float sW[EPAD];
    __shared__ float red[128];
    const int j = blockIdx.x, tid = threadIdx.x;
    for (int e = tid; e < EPAD; e += 128) sW[e] = (e < ENC) ? Wih[(size_t)j * ENC + e] : 0.f;
    __syncthreads();
    const int d = j & 511, gate = j >> 9, n = d * 4 + gate;
    for (int k = tid; k < DD; k += 128) {
        float a0 = 0.f, a1 = 0.f, a2 = 0.f, a3 = 0.f;
        const float *wr = &g_WpT2[(size_t)k * EPAD];
        for (int e = 0; e < EPAD; e += 4) {
            const float4 wv = *(const float4 *)&wr[e];
            const float4 sv = *(const float4 *)&sW[e];
            a0 += sv.x * wv.x; a1 += sv.y * wv.y; a2 += sv.z * wv.z; a3 += sv.w * wv.w;
        }
        g_WD[(size_t)k * NG + n] = (a0 + a1) + (a2 + a3) + Whh[(size_t)j * DD + k];
    }
    float p = 0.f;
    for (int e = tid; e < ENC; e += 128) p += sW[e] * bp[e];
    red[tid] = p; __syncthreads();
    for (int off = 64; off; off >>= 1) { if (tid < off) red[tid] += red[tid + off]; __syncthreads(); }
    if (tid == 0) g_biasd[n] = g_bias[n] + red[0];
}

// ==================== parallel input projection: xg[t][b][n] ====================
__global__ __launch_bounds__(256) void xg_proj(const float *__restrict__ x)
{
    __shared__ float Us[2][8 * 132];
    __shared__ float Ws[2][8 * 128];
    const int t = blockIdx.y, nbase = blockIdx.x * 128, tid = threadIdx.x;
    const int tm8 = (tid >> 4) * 8, tn8 = (tid & 15) * 8;
    const float *xbase = x + (size_t)t * ENC;

    Slots s; make_slots(s, tid);
    float2 acc[8][4];
#pragma unroll
    for (int r = 0; r < 8; ++r)
#pragma unroll
        for (int c = 0; c < 4; ++c) acc[r][c] = make_float2(0.f, 0.f);

    float ur[4], wr[4];
    auto load = [&](int kb) {
#pragma unroll
        for (int p = 0; p < 4; ++p) {
            int k = kb + s.klp[p];
            ur[p] = (k < ENC) ? __ldg(&xbase[(size_t)s.mmp[p] * XSTR + k]) : 0.f;
            wr[p] = g_WX[(size_t)(kb + s.kwp[p]) * NG + nbase + s.nlp[p]];
        }
    };

    int buf = 0;
    load(0);
    stage(s, ur, wr, Us[0], Ws[0]);
    __syncthreads();
#pragma unroll 1
    for (int c8 = 0; c8 < 41; ++c8) {
        if (c8 < 40) load((c8 + 1) * 8);
        mma8(acc, Us[buf], Ws[buf], tm8, tn8);
        if (c8 < 40) { stage(s, ur, wr, Us[buf ^ 1], Ws[buf ^ 1]); __syncthreads(); buf ^= 1; }
    }
#pragma unroll
    for (int r = 0; r < 8; ++r) {
        float *dst = &g_xg[((size_t)t * BB + tm8 + r) * NG + nbase + tn8];
        *(float4 *)dst       = make_float4(acc[r][0].x, acc[r][0].y, acc[r][1].x, acc[r][1].y);
        *(float4 *)(dst + 4) = make_float4(acc[r][2].x, acc[r][2].y, acc[r][3].x, acc[r][3].y);
    }
}

// ==================== persistent recurrent kernel (fused gemm + cell) ====================
// 128 blocks x 256 threads. Block bx owns gate-cols [16bx,16bx+16) == d in [4bx,4bx+4).
// Thread (mg=tid>>2, ng=tid&3): batches 2mg,2mg+1, head-dim d=4bx+ng, all 4 gates in regs.
__global__ __launch_bounds__(256, 1) void lstm_persistent()
{
    __shared__ float Ws[DD * 16];       // weight strip, persistent per phase (32 KB)
    __shared__ float Us[2][8 * 132];    // h chunk double buffer [k][m]

    const int tid = threadIdx.x, bx = blockIdx.x;
    const int ng = tid & 3, mg = tid >> 2;
    const int m0 = 2 * mg;
    const int d  = 4 * bx + ng;
    const int qs = tid & 1, mr = tid >> 1;      // staging geometry

    // load encoder weight strip + bias
    for (int i = tid; i < DD * 16; i += 256) {
        int k = i >> 4, j = i & 15;
        Ws[i] = g_WE[(size_t)k * NG + bx * 16 + j];
    }
    float4 bias = *(const float4 *)&g_bias[4 * d];
    float c0 = 0.f, c1 = 0.f;
    __syncthreads();

    for (int st = 0; st < SEQ + PRED - 1; ++st) {
        const bool enc = (st < SEQ);
        if (st == SEQ) {                         // switch to decoder weights
            for (int i = tid; i < DD * 16; i += 256) {
                int k = i >> 4, j = i & 15;
                Ws[i] = g_WD[(size_t)k * NG + bx * 16 + j];
            }
            bias = *(const float4 *)&g_biasd[4 * d];
            __syncthreads();
        }
        const float *hr = g_h[st & 1];
        float *hw = g_h[(st & 1) ^ 1];

        // prefetch xg for this thread's two cells (encoder only) — held across K-loop
        float4 xa0 = make_float4(0.f, 0.f, 0.f, 0.f), xa1 = xa0;
        if (enc) {
            xa0 = __ldcg((const float4 *)&g_xg[((size_t)st * BB + m0) * NG + 4 * d]);
            xa1 = __ldcg((const float4 *)&g_xg[((size_t)st * BB + m0 + 1) * NG + 4 * d]);
        }

        float2 acc00 = {0.f, 0.f}, acc01 = acc00, acc10 = acc00, acc11 = acc00;

        // depth-4 register pipeline of A (h) chunks; 64 chunks of BK=8
        float4 p[4];
#pragma unroll
        for (int cc = 0; cc < 4; ++cc)
            p[cc] = __ldcg((const float4 *)&hr[mr * DD + cc * 8 + 4 * qs]);
        {   // stage chunk 0
            float *u = &Us[0][(4 * qs) * 132 + mr];
            u[0] = p[0].x; u[132] = p[0].y; u[264] = p[0].z; u[396] = p[0].w;
        }
        __syncthreads();

#pragma unroll 1
        for (int ch = 0; ch < 64; ++ch) {
            if (ch + 4 < 64)
                p[ch & 3] = __ldcg((const float4 *)&hr[mr * DD + (ch + 4) * 8 + 4 * qs]);
            if (ch < 63) {
                float4 v = p[(ch + 1) & 3];
                float *u = &Us[(ch + 1) & 1][(4 * qs) * 132 + mr];
                u[0] = v.x; u[132] = v.y; u[264] = v.z; u[396] = v.w;
            }
            const float *ub = Us[ch & 1];
            const float *wb = &Ws[(ch * 8) * 16 + 4 * ng];
#pragma unroll
            for (int k = 0; k < 8; ++k) {
                float2 a = *(const float2 *)&ub[k * 132 + m0];
                float4 b = *(const float4 *)&wb[k * 16];
                float2 blo = make_float2(b.x, b.y), bhi = make_float2(b.z, b.w);
                fma2(acc00, make_float2(a.x, a.x), blo);
                fma2(acc01, make_float2(a.x, a.x), bhi);
                fma2(acc10, make_float2(a.y, a.y), blo);
                fma2(acc11, make_float2(a.y, a.y), bhi);
            }
            __syncthreads();
        }

        // fused LSTM cell update — gates (i,f,g,o) live in this thread's registers
        {
            float gi = acc00.x + bias.x + xa0.x;
            float gf = acc00.y + bias.y + xa0.y;
            float gg = acc01.x + bias.z + xa0.z;
            float go = acc01.y + bias.w + xa0.w;
            c0 = sigm(gf) * c0 + sigm(gi) * tanhf(gg);
            float h0 = sigm(go) * tanhf(c0);

            gi = acc10.x + bias.x + xa1.x;
            gf = acc10.y + bias.y + xa1.y;
            gg = acc11.x + bias.z + xa1.z;
            go = acc11.y + bias.w + xa1.w;
            c1 = sigm(gf) * c1 + sigm(gi) * tanhf(gg);
            float h1 = sigm(go) * tanhf(c1);

            hw[m0 * DD + d]       = h0;
            hw[(m0 + 1) * DD + d] = h1;

            float *hist = nullptr;
            if (!enc)                hist = &g_hist[(size_t)(st - SEQ + 1) * BB * DD];
            else if (st == SEQ - 1)  hist = &g_hist[0];
            if (hist) { hist[m0 * DD + d] = h0; hist[(m0 + 1) * DD + d] = h1; }
        }
        grid_sync();
    }
}

// ==================== batched output projection ====================
__global__ __launch_bounds__(256) void final_pred(const float *__restrict__ bp,
                                                  float *__restrict__ out)
{
    __shared__ float As[2][8 * 132];
    __shared__ float Bs[2][8 * 128];
    const int t = blockIdx.y, ebase = blockIdx.x * 128, tid = threadIdx.x;
    const int tm8 = (tid >> 4) * 8, tn8 = (tid & 15) * 8;
    const float *A = g_hist + (size_t)t * BB * DD;

    Slots s; make_slots(s, tid);
    float2 acc[8][4];
#pragma unroll
    for (int r = 0; r < 8; ++r)
#pragma unroll
        for (int c = 0; c < 4; ++c) acc[r][c] = make_float2(0.f, 0.f);

    float ar[4], br[4];
    auto load = [&](int kb) {
#pragma unroll
        for (int p = 0; p < 4; ++p) {
            ar[p] = A[(size_t)s.mmp[p] * DD + kb + s.klp[p]];
            br[p] = g_WpT2[(size_t)(kb + s.kwp[p]) * EPAD + ebase + s.nlp[p]];
        }
    };

    int buf = 0;
    load(0);
    stage(s, ar, br, As[0], Bs[0]);
    __syncthreads();
#pragma unroll 1
    for (int c8 = 0; c8 < 64; ++c8) {
        if (c8 < 63) load((c8 + 1) * 8);
        mma8(acc, As[buf], Bs[buf], tm8, tn8);
        if (c8 < 63) { stage(s, ar, br, As[buf ^ 1], Bs[buf ^ 1]); __syncthreads(); buf ^= 1; }
    }
#pragma unroll
    for (int r = 0; r < 8; ++r) {
        int b = tm8 + r;
        float *orow = out + ((size_t)b * PRED + t) * ENC;
        float vals[8] = {acc[r][0].x, acc[r][0].y, acc[r][1].x, acc[r][1].y,
                         acc[r][2].x, acc[r][2].y, acc[r][3].x, acc[r][3].y};
#pragma unroll
        for (int c = 0; c < 8; ++c) {
            int e = ebase + tn8 + c;
            if (e < ENC) orow[e] = vals[c] + bp[e];
        }
    }
}

extern "C" void kernel_launch(void *const *d_in, const int *in_sizes, int n_in,
                              void *d_out, int out_size)
{
    const float *x   = (const float *)d_in[0];
    const float *Wih = (const float *)d_in[1];
    const float *Whh = (const float *)d_in[2];
    const float *bih = (const float *)d_in[3];
    const float *bhh = (const float *)d_in[4];
    const float *Wp  = (const float *)d_in[5];
    const float *bp  = (const float *)d_in[6];
    float *out = (float *)d_out;

    prepA<<<4096, 256>>>(Wih, Whh, bih, bhh, Wp);
    prepB<<<NG, 128>>>(Wih, Whh, bp);
    xg_proj<<<dim3(16, SEQ), 256>>>(x);
    lstm_persistent<<<NBLK, 256>>>();
    final_pred<<<dim3(3, PRED), 256>>>(bp, out);
}

// round 7
// speedup vs baseline: 1.3708x; 1.3708x over previous
#include <cuda_runtime.h>
#include <cstdint>
#include <cstddef>

#define BB   128
#define SEQ  720
#define PRED 336
#define ENC  321
#define DD   512
#define NG   2048           // 4*D
#define XSTR (SEQ*ENC)
#define KXP  328            // ENC padded to 41*8
#define EPAD 384            // ENC padded for W_pred^T tiles
#define NBLK 128            // persistent grid

// -------- persistent device scratch --------
__device__ float g_WX  [KXP * NG];        // Wih^T gate-interleaved [k][n], n=d*4+gate
__device__ float g_WE  [DD * NG];         // Whh^T gate-interleaved
__device__ float g_WD  [DD * NG];         // decoder (Wih@Wp + Whh)^T gate-interleaved
__device__ float g_WpT2[DD * EPAD];       // W_pred^T padded [k][e]
__device__ float g_bias [NG];
__device__ float g_biasd[NG];
__device__ float g_h[2][BB * DD];                     // ping-pong hidden state
__device__ float g_xg[(size_t)SEQ * BB * NG];         // precomputed x projections
__device__ float g_hist[(size_t)PRED * BB * DD];      // decoder h_t log

__device__ volatile unsigned g_bar_gen;
__device__ unsigned g_bar_cnt;

// -------- packed fp32x2 FMA --------
__device__ __forceinline__ void fma2(float2 &d, float2 a, float2 b) {
    unsigned long long &du = reinterpret_cast<unsigned long long &>(d);
    unsigned long long au  = reinterpret_cast<unsigned long long &>(a);
    unsigned long long bu  = reinterpret_cast<unsigned long long &>(b);
    asm("fma.rn.f32x2 %0, %1, %2, %0;" : "+l"(du) : "l"(au), "l"(bu));
}

__device__ __forceinline__ float sigm(float x) { return 1.f / (1.f + __expf(-x)); }

// -------- grid barrier (one per step) --------
__device__ __forceinline__ void grid_sync() {
    __syncthreads();
    if (threadIdx.x == 0) {
        __threadfence();
        unsigned gen = g_bar_gen;
        if (atomicAdd(&g_bar_cnt, 1u) == NBLK - 1) {
            g_bar_cnt = 0;
            __threadfence();
            g_bar_gen = gen + 1;
        } else {
            int sp = 0;
            while (g_bar_gen == gen) { if (++sp > 100) __nanosleep(40); }
        }
        __threadfence();
    }
    __syncthreads();
}

// -------- GEMM micro-kernel pieces (xg_proj / final_pred) --------
struct Slots { int klp[4], mmp[4], kwp[4], nlp[4]; };

__device__ __forceinline__ void make_slots(Slots &s, int tid) {
#pragma unroll
    for (int p = 0; p < 4; ++p) {
        int lin = tid + p * 256;
        s.klp[p] = lin & 7;   s.mmp[p] = lin >> 3;
        s.nlp[p] = lin & 127; s.kwp[p] = lin >> 7;
    }
}

__device__ __forceinline__ void stage(const Slots &s, const float *ur, const float *wr,
                                      float *U, float *W) {
#pragma unroll
    for (int p = 0; p < 4; ++p) {
        U[s.klp[p] * 132 + s.mmp[p]] = ur[p];
        W[s.kwp[p] * 128 + s.nlp[p]] = wr[p];
    }
}

__device__ __forceinline__ void mma8(float2 acc[8][4], const float *U, const float *W,
                                     int tm8, int tn8) {
#pragma unroll
    for (int q = 0; q < 8; ++q) {
        const float4 a0 = *(const float4 *)&U[q * 132 + tm8];
        const float4 a1 = *(const float4 *)&U[q * 132 + tm8 + 4];
        const float4 b0 = *(const float4 *)&W[q * 128 + tn8];
        const float4 b1 = *(const float4 *)&W[q * 128 + tn8 + 4];
        float  av[8] = {a0.x, a0.y, a0.z, a0.w, a1.x, a1.y, a1.z, a1.w};
        float2 bv[4] = {make_float2(b0.x, b0.y), make_float2(b0.z, b0.w),
                        make_float2(b1.x, b1.y), make_float2(b1.z, b1.w)};
#pragma unroll
        for (int r = 0; r < 8; ++r) {
            float2 ad = make_float2(av[r], av[r]);
#pragma unroll
            for (int c = 0; c < 4; ++c) fma2(acc[r][c], ad, bv[c]);
        }
    }
}

// ==================== prep kernels ====================
__global__ void prepA(const float *__restrict__ Wih, const float *__restrict__ Whh,
                      const float *__restrict__ bih, const float *__restrict__ bhh,
                      const float *__restrict__ Wp)
{
    int idx = blockIdx.x * 256 + threadIdx.x;
    if (idx < KXP * NG) {
        int k = idx / NG, n = idx - k * NG, d = n >> 2, gate = n & 3, j = gate * DD + d;
        g_WX[idx] = (k < ENC) ? Wih[(size_t)j * ENC + k] : 0.f;
    }
    if (idx < DD * NG) {
        int k = idx / NG, n = idx - k * NG, d = n >> 2, gate = n & 3, j = gate * DD + d;
        g_WE[idx] = Whh[(size_t)j * DD + k];
    }
    if (idx < DD * EPAD) {
        int k = idx / EPAD, e = idx - k * EPAD;
        g_WpT2[idx] = (e < ENC) ? Wp[(size_t)e * DD + k] : 0.f;
    }
    if (idx < NG) {
        int j = idx, n = (j & 511) * 4 + (j >> 9);
        g_bias[n] = bih[j] + bhh[j];
    }
    if (idx < 2 * BB * DD) ((float *)g_h)[idx] = 0.f;
}

// g_WD[k][n] = sum_e Wih[j][e]*Wp[e][k] + Whh[j][k];  biasd[n] = bias[n] + Wih[j]·bp
__global__ void prepB(const float *__restrict__ Wih, const float *__restrict__ Whh,
                      const float *__restrict__ bp)
{
    __shared__ float sW[EPAD];
    __shared__ float red[128];
    const int j = blockIdx.x, tid = threadIdx.x;
    for (int e = tid; e < EPAD; e += 128) sW[e] = (e < ENC) ? Wih[(size_t)j * ENC + e] : 0.f;
    __syncthreads();
    const int d = j & 511, gate = j >> 9, n = d * 4 + gate;
    for (int k = tid; k < DD; k += 128) {
        float a0 = 0.f, a1 = 0.f, a2 = 0.f, a3 = 0.f;
        const float *wr = &g_WpT2[(size_t)k * EPAD];
        for (int e = 0; e < EPAD; e += 4) {
            const float4 wv = *(const float4 *)&wr[e];
            const float4 sv = *(const float4 *)&sW[e];
            a0 += sv.x * wv.x; a1 += sv.y * wv.y; a2 += sv.z * wv.z; a3 += sv.w * wv.w;
        }
        g_WD[(size_t)k * NG + n] = (a0 + a1) + (a2 + a3) + Whh[(size_t)j * DD + k];
    }
    float p = 0.f;
    for (int e = tid; e < ENC; e += 128) p += sW[e] * bp[e];
    red[tid] = p; __syncthreads();
    for (int off = 64; off; off >>= 1) { if (tid < off) red[tid] += red[tid + off]; __syncthreads(); }
    if (tid == 0) g_biasd[n] = g_bias[n] + red[0];
}

// ==================== parallel input projection: xg[t][b][n] ====================
__global__ __launch_bounds__(256) void xg_proj(const float *__restrict__ x)
{
    __shared__ float Us[2][8 * 132];
    __shared__ float Ws[2][8 * 128];
    const int t = blockIdx.y, nbase = blockIdx.x * 128, tid = threadIdx.x;
    const int tm8 = (tid >> 4) * 8, tn8 = (tid & 15) * 8;
    const float *xbase = x + (size_t)t * ENC;

    Slots s; make_slots(s, tid);
    float2 acc[8][4];
#pragma unroll
    for (int r = 0; r < 8; ++r)
#pragma unroll
        for (int c = 0; c < 4; ++c) acc[r][c] = make_float2(0.f, 0.f);

    float ur[4], wr[4];
    auto load = [&](int kb) {
#pragma unroll
        for (int p = 0; p < 4; ++p) {
            int k = kb + s.klp[p];
            ur[p] = (k < ENC) ? __ldg(&xbase[(size_t)s.mmp[p] * XSTR + k]) : 0.f;
            wr[p] = g_WX[(size_t)(kb + s.kwp[p]) * NG + nbase + s.nlp[p]];
        }
    };

    int buf = 0;
    load(0);
    stage(s, ur, wr, Us[0], Ws[0]);
    __syncthreads();
#pragma unroll 1
    for (int c8 = 0; c8 < 41; ++c8) {
        if (c8 < 40) load((c8 + 1) * 8);
        mma8(acc, Us[buf], Ws[buf], tm8, tn8);
        if (c8 < 40) { stage(s, ur, wr, Us[buf ^ 1], Ws[buf ^ 1]); __syncthreads(); buf ^= 1; }
    }
#pragma unroll
    for (int r = 0; r < 8; ++r) {
        float *dst = &g_xg[((size_t)t * BB + tm8 + r) * NG + nbase + tn8];
        *(float4 *)dst       = make_float4(acc[r][0].x, acc[r][0].y, acc[r][1].x, acc[r][1].y);
        *(float4 *)(dst + 4) = make_float4(acc[r][2].x, acc[r][2].y, acc[r][3].x, acc[r][3].y);
    }
}

// ==================== persistent recurrent kernel (sync-free K-loop) ====================
// 128 blocks x 512 threads. Block bx owns gate-cols [16bx,16bx+16) == d in [4bx,4bx+4).
// Thread (m = tid>>2, ng = tid&3) owns batch m, head-dim d = 4bx+ng, ALL 4 gates.
// A-operand = h[m,:] fetched cooperatively by the 4-lane group via LDG + shfl(width=4).
// Weights resident in smem for the whole phase. No __syncthreads in the K-loop.
__global__ __launch_bounds__(512, 1) void lstm_persistent()
{
    __shared__ float Ws[DD * 16];       // [k][16] weight strip, 32 KB

    const int tid = threadIdx.x, bx = blockIdx.x;
    const int ng = tid & 3;
    const int m  = tid >> 2;            // 0..127
    const int d  = 4 * bx + ng;

    // load encoder weight strip + bias
    for (int i = tid; i < DD * 16; i += 512) {
        int k = i >> 4, j = i & 15;
        Ws[i] = g_WE[(size_t)k * NG + bx * 16 + j];
    }
    float4 bias = *(const float4 *)&g_bias[4 * d];
    float c0 = 0.f;
    __syncthreads();

    for (int st = 0; st < SEQ + PRED - 1; ++st) {
        const bool enc = (st < SEQ);
        if (st == SEQ) {                 // switch to decoder weights
            __syncthreads();
            for (int i = tid; i < DD * 16; i += 512) {
                int k = i >> 4, j = i & 15;
                Ws[i] = g_WD[(size_t)k * NG + bx * 16 + j];
            }
            bias = *(const float4 *)&g_biasd[4 * d];
            __syncthreads();
        }
        const float *hr = g_h[st & 1];
        float *hw = g_h[(st & 1) ^ 1];

        // prefetch xg contribution (encoder only); consumed after the K-loop
        float4 xa = make_float4(0.f, 0.f, 0.f, 0.f);
        if (enc)
            xa = __ldcg((const float4 *)&g_xg[((size_t)st * BB + m) * NG + 4 * d]);

        float2 aif = {0.f, 0.f}, ago = {0.f, 0.f};   // (i,f) and (g,o) accumulators

        const float4 *hrow = (const float4 *)&hr[m * DD];   // 128 float4 = K=512
        float4 hv = __ldcg(&hrow[ng]);                       // chunk 0, this lane's quad
#pragma unroll 1
        for (int ch = 0; ch < 32; ++ch) {
            float4 cur = hv;
            if (ch < 31) hv = __ldcg(&hrow[(ch + 1) * 4 + ng]);   // prefetch next chunk
            const float *wb = &Ws[ch * 16 * 16 + 4 * ng];
#pragma unroll
            for (int q = 0; q < 4; ++q) {
                float a0 = __shfl_sync(0xffffffffu, cur.x, q, 4);
                float a1 = __shfl_sync(0xffffffffu, cur.y, q, 4);
                float a2 = __shfl_sync(0xffffffffu, cur.z, q, 4);
                float a3 = __shfl_sync(0xffffffffu, cur.w, q, 4);
                const float4 b0 = *(const float4 *)&wb[(q * 4 + 0) * 16];
                const float4 b1 = *(const float4 *)&wb[(q * 4 + 1) * 16];
                const float4 b2 = *(const float4 *)&wb[(q * 4 + 2) * 16];
                const float4 b3 = *(const float4 *)&wb[(q * 4 + 3) * 16];
                fma2(aif, make_float2(a0, a0), make_float2(b0.x, b0.y));
                fma2(ago, make_float2(a0, a0), make_float2(b0.z, b0.w));
                fma2(aif, make_float2(a1, a1), make_float2(b1.x, b1.y));
                fma2(ago, make_float2(a1, a1), make_float2(b1.z, b1.w));
                fma2(aif, make_float2(a2, a2), make_float2(b2.x, b2.y));
                fma2(ago, make_float2(a2, a2), make_float2(b2.z, b2.w));
                fma2(aif, make_float2(a3, a3), make_float2(b3.x, b3.y));
                fma2(ago, make_float2(a3, a3), make_float2(b3.z, b3.w));
            }
        }

        // fused LSTM cell — all 4 gates of (m, d) in this thread's registers
        {
            float gi = aif.x + bias.x + xa.x;
            float gf = aif.y + bias.y + xa.y;
            float gg = ago.x + bias.z + xa.z;
            float go = ago.y + bias.w + xa.w;
            c0 = sigm(gf) * c0 + sigm(gi) * tanhf(gg);
            float h0 = sigm(go) * tanhf(c0);
            hw[m * DD + d] = h0;

            float *hist = nullptr;
            if (!enc)               hist = &g_hist[(size_t)(st - SEQ + 1) * BB * DD];
            else if (st == SEQ - 1) hist = &g_hist[0];
            if (hist) hist[m * DD + d] = h0;
        }
        grid_sync();
    }
}

// ==================== batched output projection ====================
__global__ __launch_bounds__(256) void final_pred(const float *__restrict__ bp,
                                                  float *__restrict__ out)
{
    __shared__ float As[2][8 * 132];
    __shared__ float Bs[2][8 * 128];
    const int t = blockIdx.y, ebase = blockIdx.x * 128, tid = threadIdx.x;
    const int tm8 = (tid >> 4) * 8, tn8 = (tid & 15) * 8;
    const float *A = g_hist + (size_t)t * BB * DD;

    Slots s; make_slots(s, tid);
    float2 acc[8][4];
#pragma unroll
    for (int r = 0; r < 8; ++r)
#pragma unroll
        for (int c = 0; c < 4; ++c) acc[r][c] = make_float2(0.f, 0.f);

    float ar[4], br[4];
    auto load = [&](int kb) {
#pragma unroll
        for (int p = 0; p < 4; ++p) {
            ar[p] = A[(size_t)s.mmp[p] * DD + kb + s.klp[p]];
            br[p] = g_WpT2[(size_t)(kb + s.kwp[p]) * EPAD + ebase + s.nlp[p]];
        }
    };

    int buf = 0;
    load(0);
    stage(s, ar, br, As[0], Bs[0]);
    __syncthreads();
#pragma unroll 1
    for (int c8 = 0; c8 < 64; ++c8) {
        if (c8 < 63) load((c8 + 1) * 8);
        mma8(acc, As[buf], Bs[buf], tm8, tn8);
        if (c8 < 63) { stage(s, ar, br, As[buf ^ 1], Bs[buf ^ 1]); __syncthreads(); buf ^= 1; }
    }
#pragma unroll
    for (int r = 0; r < 8; ++r) {
        int b = tm8 + r;
        float *orow = out + ((size_t)b * PRED + t) * ENC;
        float vals[8] = {acc[r][0].x, acc[r][0].y, acc[r][1].x, acc[r][1].y,
                         acc[r][2].x, acc[r][2].y, acc[r][3].x, acc[r][3].y};
#pragma unroll
        for (int c = 0; c < 8; ++c) {
            int e = ebase + tn8 + c;
            if (e < ENC) orow[e] = vals[c] + bp[e];
        }
    }
}

extern "C" void kernel_launch(void *const *d_in, const int *in_sizes, int n_in,
                              void *d_out, int out_size)
{
    const float *x   = (const float *)d_in[0];
    const float *Wih = (const float *)d_in[1];
    const float *Whh = (const float *)d_in[2];
    const float *bih = (const float *)d_in[3];
    const float *bhh = (const float *)d_in[4];
    const float *Wp  = (const float *)d_in[5];
    const float *bp  = (const float *)d_in[6];
    float *out = (float *)d_out;

    prepA<<<4096, 256>>>(Wih, Whh, bih, bhh, Wp);
    prepB<<<NG, 128>>>(Wih, Whh, bp);
    xg_proj<<<dim3(16, SEQ), 256>>>(x);
    lstm_persistent<<<NBLK, 512>>>();
    final_pred<<<dim3(3, PRED), 256>>>(bp, out);
}

// round 8
// speedup vs baseline: 1.9873x; 1.4498x over previous
#include <cuda_runtime.h>
#include <cstdint>
#include <cstddef>

#define BB   128
#define SEQ  720
#define PRED 336
#define ENC  321
#define DD   512
#define NG   2048           // 4*D
#define XSTR (SEQ*ENC)
#define KXP  328            // ENC padded to 41*8
#define EPAD 384            // ENC padded for W_pred^T tiles
#define NBLK 128            // persistent grid

// -------- persistent device scratch --------
__device__ float g_WX  [KXP * NG];        // Wih^T gate-interleaved [k][n], n=d*4+gate
__device__ float g_WE  [DD * NG];         // Whh^T gate-interleaved
__device__ float g_WD  [DD * NG];         // decoder (Wih@Wp + Whh)^T gate-interleaved
__device__ float g_WpT2[DD * EPAD];       // W_pred^T padded [k][e]
__device__ float g_bias [NG];
__device__ float g_biasd[NG];
__device__ float g_hT[2][DD * BB];        // ping-pong hidden state, TRANSPOSED [k][m]
__device__ float g_xg[(size_t)SEQ * BB * NG];         // precomputed x projections
__device__ float g_hist[(size_t)PRED * BB * DD];      // decoder h_t log ([t][m][dim])

__device__ volatile unsigned g_bar_gen;
__device__ unsigned g_bar_cnt;

// -------- packed fp32x2 FMA --------
__device__ __forceinline__ void fma2(float2 &d, float2 a, float2 b) {
    unsigned long long &du = reinterpret_cast<unsigned long long &>(d);
    unsigned long long au  = reinterpret_cast<unsigned long long &>(a);
    unsigned long long bu  = reinterpret_cast<unsigned long long &>(b);
    asm("fma.rn.f32x2 %0, %1, %2, %0;" : "+l"(du) : "l"(au), "l"(bu));
}

__device__ __forceinline__ float sigm(float x) { return 1.f / (1.f + __expf(-x)); }

// -------- grid barrier (one per step) --------
__device__ __forceinline__ void grid_sync() {
    __syncthreads();
    if (threadIdx.x == 0) {
        __threadfence();
        unsigned gen = g_bar_gen;
        if (atomicAdd(&g_bar_cnt, 1u) == NBLK - 1) {
            g_bar_cnt = 0;
            __threadfence();
            g_bar_gen = gen + 1;
        } else {
            int sp = 0;
            while (g_bar_gen == gen) { if (++sp > 100) __nanosleep(40); }
        }
        __threadfence();
    }
    __syncthreads();
}

// -------- GEMM micro-kernel pieces (xg_proj / final_pred) --------
struct Slots { int klp[4], mmp[4], kwp[4], nlp[4]; };

__device__ __forceinline__ void make_slots(Slots &s, int tid) {
#pragma unroll
    for (int p = 0; p < 4; ++p) {
        int lin = tid + p * 256;
        s.klp[p] = lin & 7;   s.mmp[p] = lin >> 3;
        s.nlp[p] = lin & 127; s.kwp[p] = lin >> 7;
    }
}

__device__ __forceinline__ void stage(const Slots &s, const float *ur, const float *wr,
                                      float *U, float *W) {
#pragma unroll
    for (int p = 0; p < 4; ++p) {
        U[s.klp[p] * 132 + s.mmp[p]] = ur[p];
        W[s.kwp[p] * 128 + s.nlp[p]] = wr[p];
    }
}

__device__ __forceinline__ void mma8(float2 acc[8][4], const float *U, const float *W,
                                     int tm8, int tn8) {
#pragma unroll
    for (int q = 0; q < 8; ++q) {
        const float4 a0 = *(const float4 *)&U[q * 132 + tm8];
        const float4 a1 = *(const float4 *)&U[q * 132 + tm8 + 4];
        const float4 b0 = *(const float4 *)&W[q * 128 + tn8];
        const float4 b1 = *(const float4 *)&W[q * 128 + tn8 + 4];
        float  av[8] = {a0.x, a0.y, a0.z, a0.w, a1.x, a1.y, a1.z, a1.w};
        float2 bv[4] = {make_float2(b0.x, b0.y), make_float2(b0.z, b0.w),
                        make_float2(b1.x, b1.y), make_float2(b1.z, b1.w)};
#pragma unroll
        for (int r = 0; r < 8; ++r) {
            float2 ad = make_float2(av[r], av[r]);
#pragma unroll
            for (int c = 0; c < 4; ++c) fma2(acc[r][c], ad, bv[c]);
        }
    }
}

// ==================== prep kernels ====================
__global__ void prepA(const float *__restrict__ Wih, const float *__restrict__ Whh,
                      const float *__restrict__ bih, const float *__restrict__ bhh,
                      const float *__restrict__ Wp)
{
    int idx = blockIdx.x * 256 + threadIdx.x;
    if (idx < KXP * NG) {
        int k = idx / NG, n = idx - k * NG, d = n >> 2, gate = n & 3, j = gate * DD + d;
        g_WX[idx] = (k < ENC) ? Wih[(size_t)j * ENC + k] : 0.f;
    }
    if (idx < DD * NG) {
        int k = idx / NG, n = idx - k * NG, d = n >> 2, gate = n & 3, j = gate * DD + d;
        g_WE[idx] = Whh[(size_t)j * DD + k];
    }
    if (idx < DD * EPAD) {
        int k = idx / EPAD, e = idx - k * EPAD;
        g_WpT2[idx] = (e < ENC) ? Wp[(size_t)e * DD + k] : 0.f;
    }
    if (idx < NG) {
        int j = idx, n = (j & 511) * 4 + (j >> 9);
        g_bias[n] = bih[j] + bhh[j];
    }
    if (idx < 2 * BB * DD) ((float *)g_hT)[idx] = 0.f;
}

// g_WD[k][n] = sum_e Wih[j][e]*Wp[e][k] + Whh[j][k];  biasd[n] = bias[n] + Wih[j]·bp
__global__ void prepB(const float *__restrict__ Wih, const float *__restrict__ Whh,
                      const float *__restrict__ bp)
{
    __shared__ float sW[EPAD];
    __shared__ float red[128];
    const int j = blockIdx.x, tid = threadIdx.x;
    for (int e = tid; e < EPAD; e += 128) sW[e] = (e < ENC) ? Wih[(size_t)j * ENC + e] : 0.f;
    __syncthreads();
    const int d = j & 511, gate = j >> 9, n = d * 4 + gate;
    for (int k = tid; k < DD; k += 128) {
        float a0 = 0.f, a1 = 0.f, a2 = 0.f, a3 = 0.f;
        const float *wr = &g_WpT2[(size_t)k * EPAD];
        for (int e = 0; e < EPAD; e += 4) {
            const float4 wv = *(const float4 *)&wr[e];
            const float4 sv = *(const float4 *)&sW[e];
            a0 += sv.x * wv.x; a1 += sv.y * wv.y; a2 += sv.z * wv.z; a3 += sv.w * wv.w;
        }
        g_WD[(size_t)k * NG + n] = (a0 + a1) + (a2 + a3) + Whh[(size_t)j * DD + k];
    }
    float p = 0.f;
    for (int e = tid; e < ENC; e += 128) p += sW[e] * bp[e];
    red[tid] = p; __syncthreads();
    for (int off = 64; off; off >>= 1) { if (tid < off) red[tid] += red[tid + off]; __syncthreads(); }
    if (tid == 0) g_biasd[n] = g_bias[n] + red[0];
}

// ==================== parallel input projection: xg[t][b][n] ====================
__global__ __launch_bounds__(256) void xg_proj(const float *__restrict__ x)
{
    __shared__ float Us[2][8 * 132];
    __shared__ float Ws[2][8 * 128];
    const int t = blockIdx.y, nbase = blockIdx.x * 128, tid = threadIdx.x;
    const int tm8 = (tid >> 4) * 8, tn8 = (tid & 15) * 8;
    const float *xbase = x + (size_t)t * ENC;

    Slots s; make_slots(s, tid);
    float2 acc[8][4];
#pragma unroll
    for (int r = 0; r < 8; ++r)
#pragma unroll
        for (int c = 0; c < 4; ++c) acc[r][c] = make_float2(0.f, 0.f);

    float ur[4], wr[4];
    auto load = [&](int kb) {
#pragma unroll
        for (int p = 0; p < 4; ++p) {
            int k = kb + s.klp[p];
            ur[p] = (k < ENC) ? __ldg(&xbase[(size_t)s.mmp[p] * XSTR + k]) : 0.f;
            wr[p] = g_WX[(size_t)(kb + s.kwp[p]) * NG + nbase + s.nlp[p]];
        }
    };

    int buf = 0;
    load(0);
    stage(s, ur, wr, Us[0], Ws[0]);
    __syncthreads();
#pragma unroll 1
    for (int c8 = 0; c8 < 41; ++c8) {
        if (c8 < 40) load((c8 + 1) * 8);
        mma8(acc, Us[buf], Ws[buf], tm8, tn8);
        if (c8 < 40) { stage(s, ur, wr, Us[buf ^ 1], Ws[buf ^ 1]); __syncthreads(); buf ^= 1; }
    }
#pragma unroll
    for (int r = 0; r < 8; ++r) {
        float *dst = &g_xg[((size_t)t * BB + tm8 + r) * NG + nbase + tn8];
        *(float4 *)dst       = make_float4(acc[r][0].x, acc[r][0].y, acc[r][1].x, acc[r][1].y);
        *(float4 *)(dst + 4) = make_float4(acc[r][2].x, acc[r][2].y, acc[r][3].x, acc[r][3].y);
    }
}

// ==================== persistent recurrent kernel ====================
// 128 blocks x 256 threads (8 warps). Block bx owns gate-cols [16bx,16bx+16)
// == output dims d in [4bx,4bx+4). Warp w handles k-slice [64w, 64w+64).
// Lane L computes batches m in {4L..4L+4} x all 16 cols; A comes straight from
// transposed h (g_hT[k][m]) via coalesced LDG.128 — no smem staging, no shfl.
// Partials reduced across the 8 warps through a 16 KB smem buffer in 4 m-quarters.
// Cell state c lives in registers (thread tid<128 owns (m = 32q + tid>>2, d = tid&3)).
__global__ __launch_bounds__(256, 1) void lstm_persistent()
{
    __shared__ float Ws[DD * 16];       // weight strip [k][16], 32 KB
    __shared__ float part[8 * 512];     // per-warp quarter partials, 16 KB

    const int tid = threadIdx.x, bx = blockIdx.x;
    const int w = tid >> 5, lane = tid & 31;
    const int k0 = w * 64;
    const int rm = tid >> 2, rd = tid & 3;      // reduce role (tid<128): m' = rm, d = rd

    for (int i = tid; i < DD * 16; i += 256)
        Ws[i] = g_WE[(size_t)(i >> 4) * NG + bx * 16 + (i & 15)];
    float4 bias = *(const float4 *)&g_bias[bx * 16 + 4 * rd];
    float cst[4] = {0.f, 0.f, 0.f, 0.f};
    __syncthreads();

    for (int st = 0; st < SEQ + PRED - 1; ++st) {
        const bool enc = (st < SEQ);
        if (st == SEQ) {
            __syncthreads();
            for (int i = tid; i < DD * 16; i += 256)
                Ws[i] = g_WD[(size_t)(i >> 4) * NG + bx * 16 + (i & 15)];
            bias = *(const float4 *)&g_biasd[bx * 16 + 4 * rd];
            __syncthreads();
        }
        const float4 *hb = (const float4 *)g_hT[st & 1];
        float *hw = g_hT[(st & 1) ^ 1];

        // prefetch xg for this thread's 4 (quarter) cells — overlaps the GEMM
        float4 xa[4];
#pragma unroll
        for (int q = 0; q < 4; ++q) xa[q] = make_float4(0.f, 0.f, 0.f, 0.f);
        if (enc && tid < 128) {
#pragma unroll
            for (int q = 0; q < 4; ++q)
                xa[q] = __ldcg((const float4 *)
                    &g_xg[((size_t)st * BB + 32 * q + rm) * NG + bx * 16 + 4 * rd]);
        }

        // ---- GEMM: acc[i][c] = sum_k h[m=4*lane+i][k] * W[k][2c..2c+2) over k-slice
        float2 acc[4][8];
#pragma unroll
        for (int i = 0; i < 4; ++i)
#pragma unroll
            for (int c = 0; c < 8; ++c) acc[i][c] = make_float2(0.f, 0.f);

        float4 pf[8];
#pragma unroll
        for (int j = 0; j < 8; ++j)
            pf[j] = __ldcg(&hb[(k0 + j) * 32 + lane]);

#pragma unroll 4
        for (int k = 0; k < 64; ++k) {
            float4 hv = pf[k & 7];
            int kn = (k + 8 < 64) ? k + 8 : k;
            pf[k & 7] = __ldcg(&hb[(k0 + kn) * 32 + lane]);
            const float4 *wrow = (const float4 *)&Ws[(k0 + k) * 16];
            const float4 w0 = wrow[0], w1 = wrow[1], w2 = wrow[2], w3 = wrow[3];
            const float av[4] = {hv.x, hv.y, hv.z, hv.w};
#pragma unroll
            for (int i = 0; i < 4; ++i) {
                float2 a = make_float2(av[i], av[i]);
                fma2(acc[i][0], a, make_float2(w0.x, w0.y));
                fma2(acc[i][1], a, make_float2(w0.z, w0.w));
                fma2(acc[i][2], a, make_float2(w1.x, w1.y));
                fma2(acc[i][3], a, make_float2(w1.z, w1.w));
                fma2(acc[i][4], a, make_float2(w2.x, w2.y));
                fma2(acc[i][5], a, make_float2(w2.z, w2.w));
                fma2(acc[i][6], a, make_float2(w3.x, w3.y));
                fma2(acc[i][7], a, make_float2(w3.z, w3.w));
            }
        }
        __syncthreads();

        // ---- reduce 8 warp-partials + cell update, in 4 m-quarters of 32
#pragma unroll 1
        for (int q = 0; q < 4; ++q) {
            if (lane >= 8 * q && lane < 8 * q + 8) {
                int ml = 4 * (lane - 8 * q);          // local m within quarter
#pragma unroll
                for (int i = 0; i < 4; ++i) {
                    int mp = ml + i;
                    int sw = (mp >> 2) & 3;           // bank swizzle
#pragma unroll
                    for (int c4 = 0; c4 < 4; ++c4) {
                        float4 v = make_float4(acc[i][2 * c4].x,     acc[i][2 * c4].y,
                                               acc[i][2 * c4 + 1].x, acc[i][2 * c4 + 1].y);
                        *(float4 *)&part[w * 512 + mp * 16 + ((c4 ^ sw) * 4)] = v;
                    }
                }
            }
            __syncthreads();
            if (tid < 128) {
                int slot = (rd ^ ((rm >> 2) & 3)) * 4;
                float4 s0 = make_float4(0.f, 0.f, 0.f, 0.f);
#pragma unroll
                for (int ww = 0; ww < 8; ++ww) {
                    float4 v = *(const float4 *)&part[ww * 512 + rm * 16 + slot];
                    s0.x += v.x; s0.y += v.y; s0.z += v.z; s0.w += v.w;
                }
                int m = 32 * q + rm;
                float gi = s0.x + bias.x + xa[q].x;
                float gf = s0.y + bias.y + xa[q].y;
                float gg = s0.z + bias.z + xa[q].z;
                float go = s0.w + bias.w + xa[q].w;
                float cn = sigm(gf) * cst[q] + sigm(gi) * tanhf(gg);
                cst[q] = cn;
                float h0 = sigm(go) * tanhf(cn);
                hw[(4 * bx + rd) * BB + m] = h0;
                if (!enc)
                    g_hist[(size_t)(st - SEQ + 1) * BB * DD + (size_t)m * DD + 4 * bx + rd] = h0;
                else if (st == SEQ - 1)
                    g_hist[(size_t)m * DD + 4 * bx + rd] = h0;
            }
            __syncthreads();
        }
        grid_sync();
    }
}

// ==================== batched output projection ====================
__global__ __launch_bounds__(256) void final_pred(const float *__restrict__ bp,
                                                  float *__restrict__ out)
{
    __shared__ float As[2][8 * 132];
    __shared__ float Bs[2][8 * 128];
    const int t = blockIdx.y, ebase = blockIdx.x * 128, tid = threadIdx.x;
    const int tm8 = (tid >> 4) * 8, tn8 = (tid & 15) * 8;
    const float *A = g_hist + (size_t)t * BB * DD;

    Slots s; make_slots(s, tid);
    float2 acc[8][4];
#pragma unroll
    for (int r = 0; r < 8; ++r)
#pragma unroll
        for (int c = 0; c < 4; ++c) acc[r][c] = make_float2(0.f, 0.f);

    float ar[4], br[4];
    auto load = [&](int kb) {
#pragma unroll
        for (int p = 0; p < 4; ++p) {
            ar[p] = A[(size_t)s.mmp[p] * DD + kb + s.klp[p]];
            br[p] = g_WpT2[(size_t)(kb + s.kwp[p]) * EPAD + ebase + s.nlp[p]];
        }
    };

    int buf = 0;
    load(0);
    stage(s, ar, br, As[0], Bs[0]);
    __syncthreads();
#pragma unroll 1
    for (int c8 = 0; c8 < 64; ++c8) {
        if (c8 < 63) load((c8 + 1) * 8);
        mma8(acc, As[buf], Bs[buf], tm8, tn8);
        if (c8 < 63) { stage(s, ar, br, As[buf ^ 1], Bs[buf ^ 1]); __syncthreads(); buf ^= 1; }
    }
#pragma unroll
    for (int r = 0; r < 8; ++r) {
        int b = tm8 + r;
        float *orow = out + ((size_t)b * PRED + t) * ENC;
        float vals[8] = {acc[r][0].x, acc[r][0].y, acc[r][1].x, acc[r][1].y,
                         acc[r][2].x, acc[r][2].y, acc[r][3].x, acc[r][3].y};
#pragma unroll
        for (int c = 0; c < 8; ++c) {
            int e = ebase + tn8 + c;
            if (e < ENC) orow[e] = vals[c] + bp[e];
        }
    }
}

extern "C" void kernel_launch(void *const *d_in, const int *in_sizes, int n_in,
                              void *d_out, int out_size)
{
    const float *x   = (const float *)d_in[0];
    const float *Wih = (const float *)d_in[1];
    const float *Whh = (const float *)d_in[2];
    const float *bih = (const float *)d_in[3];
    const float *bhh = (const float *)d_in[4];
    const float *Wp  = (const float *)d_in[5];
    const float *bp  = (const float *)d_in[6];
    float *out = (float *)d_out;

    prepA<<<4096, 256>>>(Wih, Whh, bih, bhh, Wp);
    prepB<<<NG, 128>>>(Wih, Whh, bp);
    xg_proj<<<dim3(16, SEQ), 256>>>(x);
    lstm_persistent<<<NBLK, 256>>>();
    final_pred<<<dim3(3, PRED), 256>>>(bp, out);
}

// round 9
// speedup vs baseline: 2.6610x; 1.3390x over previous
#include <cuda_runtime.h>
#include <cstdint>
#include <cstddef>

#define BB   128
#define SEQ  720
#define PRED 336
#define ENC  321
#define DD   512
#define NG   2048           // 4*D
#define XSTR (SEQ*ENC)
#define KXP  328            // ENC padded to 41*8
#define EPAD 384            // ENC padded for W_pred^T tiles
#define NBLK 128            // persistent grid
#define LSTM_SMEM (32768 + 131072)   // Ws strip + 16-warp partials

// -------- persistent device scratch --------
__device__ float g_WX  [KXP * NG];        // Wih^T gate-interleaved [k][n], n=d*4+gate
__device__ float g_WE  [DD * NG];         // Whh^T gate-interleaved
__device__ float g_WD  [DD * NG];         // decoder (Wih@Wp + Whh)^T gate-interleaved
__device__ float g_WpT2[DD * EPAD];       // W_pred^T padded [k][e]
__device__ float g_bias [NG];
__device__ float g_biasd[NG];
__device__ float g_hT[2][DD * BB];        // ping-pong hidden state, TRANSPOSED [dim][m]
__device__ float g_xg[(size_t)SEQ * BB * NG];         // precomputed x projections
__device__ float g_hist[(size_t)PRED * BB * DD];      // decoder h_t log ([t][m][dim])

__device__ volatile unsigned g_bar_gen;
__device__ unsigned g_bar_cnt;

// -------- packed fp32x2 FMA --------
__device__ __forceinline__ void fma2(float2 &d, float2 a, float2 b) {
    unsigned long long &du = reinterpret_cast<unsigned long long &>(d);
    unsigned long long au  = reinterpret_cast<unsigned long long &>(a);
    unsigned long long bu  = reinterpret_cast<unsigned long long &>(b);
    asm("fma.rn.f32x2 %0, %1, %2, %0;" : "+l"(du) : "l"(au), "l"(bu));
}

__device__ __forceinline__ float sigm(float x) { return 1.f / (1.f + __expf(-x)); }

// -------- grid barrier (one per step) --------
__device__ __forceinline__ void grid_sync() {
    __syncthreads();
    if (threadIdx.x == 0) {
        __threadfence();
        unsigned gen = g_bar_gen;
        if (atomicAdd(&g_bar_cnt, 1u) == NBLK - 1) {
            g_bar_cnt = 0;
            __threadfence();
            g_bar_gen = gen + 1;
        } else {
            int sp = 0;
            while (g_bar_gen == gen) { if (++sp > 100) __nanosleep(40); }
        }
        __threadfence();
    }
    __syncthreads();
}

// -------- GEMM micro-kernel pieces (xg_proj / final_pred) --------
struct Slots { int klp[4], mmp[4], kwp[4], nlp[4]; };

__device__ __forceinline__ void make_slots(Slots &s, int tid) {
#pragma unroll
    for (int p = 0; p < 4; ++p) {
        int lin = tid + p * 256;
        s.klp[p] = lin & 7;   s.mmp[p] = lin >> 3;
        s.nlp[p] = lin & 127; s.kwp[p] = lin >> 7;
    }
}

__device__ __forceinline__ void stage(const Slots &s, const float *ur, const float *wr,
                                      float *U, float *W) {
#pragma unroll
    for (int p = 0; p < 4; ++p) {
        U[s.klp[p] * 132 + s.mmp[p]] = ur[p];
        W[s.kwp[p] * 128 + s.nlp[p]] = wr[p];
    }
}

__device__ __forceinline__ void mma8(float2 acc[8][4], const float *U, const float *W,
                                     int tm8, int tn8) {
#pragma unroll
    for (int q = 0; q < 8; ++q) {
        const float4 a0 = *(const float4 *)&U[q * 132 + tm8];
        const float4 a1 = *(const float4 *)&U[q * 132 + tm8 + 4];
        const float4 b0 = *(const float4 *)&W[q * 128 + tn8];
        const float4 b1 = *(const float4 *)&W[q * 128 + tn8 + 4];
        float  av[8] = {a0.x, a0.y, a0.z, a0.w, a1.x, a1.y, a1.z, a1.w};
        float2 bv[4] = {make_float2(b0.x, b0.y), make_float2(b0.z, b0.w),
                        make_float2(b1.x, b1.y), make_float2(b1.z, b1.w)};
#pragma unroll
        for (int r = 0; r < 8; ++r) {
            float2 ad = make_float2(av[r], av[r]);
#pragma unroll
            for (int c = 0; c < 4; ++c) fma2(acc[r][c], ad, bv[c]);
        }
    }
}

// ==================== prep kernels ====================
__global__ void prepA(const float *__restrict__ Wih, const float *__restrict__ Whh,
                      const float *__restrict__ bih, const float *__restrict__ bhh,
                      const float *__restrict__ Wp)
{
    int idx = blockIdx.x * 256 + threadIdx.x;
    if (idx < KXP * NG) {
        int k = idx / NG, n = idx - k * NG, d = n >> 2, gate = n & 3, j = gate * DD + d;
        g_WX[idx] = (k < ENC) ? Wih[(size_t)j * ENC + k] : 0.f;
    }
    if (idx < DD * NG) {
        int k = idx / NG, n = idx - k * NG, d = n >> 2, gate = n & 3, j = gate * DD + d;
        g_WE[idx] = Whh[(size_t)j * DD + k];
    }
    if (idx < DD * EPAD) {
        int k = idx / EPAD, e = idx - k * EPAD;
        g_WpT2[idx] = (e < ENC) ? Wp[(size_t)e * DD + k] : 0.f;
    }
    if (idx < NG) {
        int j = idx, n = (j & 511) * 4 + (j >> 9);
        g_bias[n] = bih[j] + bhh[j];
    }
    if (idx < 2 * BB * DD) ((float *)g_hT)[idx] = 0.f;
}

// g_WD[k][n] = sum_e Wih[j][e]*Wp[e][k] + Whh[j][k];  biasd[n] = bias[n] + Wih[j]·bp
__global__ void prepB(const float *__restrict__ Wih, const float *__restrict__ Whh,
                      const float *__restrict__ bp)
{
    __shared__ float sW[EPAD];
    __shared__ float red[128];
    const int j = blockIdx.x, tid = threadIdx.x;
    for (int e = tid; e < EPAD; e += 128) sW[e] = (e < ENC) ? Wih[(size_t)j * ENC + e] : 0.f;
    __syncthreads();
    const int d = j & 511, gate = j >> 9, n = d * 4 + gate;
    for (int k = tid; k < DD; k += 128) {
        float a0 = 0.f, a1 = 0.f, a2 = 0.f, a3 = 0.f;
        const float *wr = &g_WpT2[(size_t)k * EPAD];
        for (int e = 0; e < EPAD; e += 4) {
            const float4 wv = *(const float4 *)&wr[e];
            const float4 sv = *(const float4 *)&sW[e];
            a0 += sv.x * wv.x; a1 += sv.y * wv.y; a2 += sv.z * wv.z; a3 += sv.w * wv.w;
        }
        g_WD[(size_t)k * NG + n] = (a0 + a1) + (a2 + a3) + Whh[(size_t)j * DD + k];
    }
    float p = 0.f;
    for (int e = tid; e < ENC; e += 128) p += sW[e] * bp[e];
    red[tid] = p; __syncthreads();
    for (int off = 64; off; off >>= 1) { if (tid < off) red[tid] += red[tid + off]; __syncthreads(); }
    if (tid == 0) g_biasd[n] = g_bias[n] + red[0];
}

// ==================== parallel input projection: xg[t][b][n] ====================
__global__ __launch_bounds__(256) void xg_proj(const float *__restrict__ x)
{
    __shared__ float Us[2][8 * 132];
    __shared__ float Ws[2][8 * 128];
    const int t = blockIdx.y, nbase = blockIdx.x * 128, tid = threadIdx.x;
    const int tm8 = (tid >> 4) * 8, tn8 = (tid & 15) * 8;
    const float *xbase = x + (size_t)t * ENC;

    Slots s; make_slots(s, tid);
    float2 acc[8][4];
#pragma unroll
    for (int r = 0; r < 8; ++r)
#pragma unroll
        for (int c = 0; c < 4; ++c) acc[r][c] = make_float2(0.f, 0.f);

    float ur[4], wr[4];
    auto load = [&](int kb) {
#pragma unroll
        for (int p = 0; p < 4; ++p) {
            int k = kb + s.klp[p];
            ur[p] = (k < ENC) ? __ldg(&xbase[(size_t)s.mmp[p] * XSTR + k]) : 0.f;
            wr[p] = g_WX[(size_t)(kb + s.kwp[p]) * NG + nbase + s.nlp[p]];
        }
    };

    int buf = 0;
    load(0);
    stage(s, ur, wr, Us[0], Ws[0]);
    __syncthreads();
#pragma unroll 1
    for (int c8 = 0; c8 < 41; ++c8) {
        if (c8 < 40) load((c8 + 1) * 8);
        mma8(acc, Us[buf], Ws[buf], tm8, tn8);
        if (c8 < 40) { stage(s, ur, wr, Us[buf ^ 1], Ws[buf ^ 1]); __syncthreads(); buf ^= 1; }
    }
#pragma unroll
    for (int r = 0; r < 8; ++r) {
        float *dst = &g_xg[((size_t)t * BB + tm8 + r) * NG + nbase + tn8];
        *(float4 *)dst       = make_float4(acc[r][0].x, acc[r][0].y, acc[r][1].x, acc[r][1].y);
        *(float4 *)(dst + 4) = make_float4(acc[r][2].x, acc[r][2].y, acc[r][3].x, acc[r][3].y);
    }
}

// ==================== persistent recurrent kernel ====================
// 128 blocks x 512 threads (16 warps, 4/SMSP). Block bx owns gate-cols
// [16bx,16bx+16) == dims [4bx,4bx+4). Warp w owns k-slice [32w,32w+32);
// lane L covers batches 4L..4L+4 (float4 straight from transposed h in L2).
// Partials (16 x 128 x 16 floats, 128 KB smem) reduced once: each thread owns
// ONE cell (m = tid&127, dl = tid>>7) with c resident in a register.
__global__ __launch_bounds__(512, 1) void lstm_persistent()
{
    extern __shared__ float dsm[];
    float *Ws   = dsm;                  // [512][16]  weight strip, 32 KB
    float *part = dsm + DD * 16;        // [16][128][16] partials, 128 KB

    const int tid = threadIdx.x, bx = blockIdx.x;
    const int w = tid >> 5, lane = tid & 31;
    const int k0 = 32 * w;
    const int dl = tid >> 7;            // 0..3  (cell dim within block)
    const int mo = tid & 127;           // cell batch

    for (int i = tid; i < DD * 16; i += 512)
        Ws[i] = g_WE[(size_t)(i >> 4) * NG + bx * 16 + (i & 15)];
    float4 bias = *(const float4 *)&g_bias[bx * 16 + 4 * dl];
    float cst = 0.f;
    __syncthreads();

    for (int st = 0; st < SEQ + PRED - 1; ++st) {
        const bool enc = (st < SEQ);
        if (st == SEQ) {                 // switch to decoder weights
            for (int i = tid; i < DD * 16; i += 512)
                Ws[i] = g_WD[(size_t)(i >> 4) * NG + bx * 16 + (i & 15)];
            bias = *(const float4 *)&g_biasd[bx * 16 + 4 * dl];
            __syncthreads();
        }
        const float4 *hb = (const float4 *)g_hT[st & 1];
        float *hw = g_hT[(st & 1) ^ 1];

        // prefetch xg for this thread's cell — consumed after the GEMM
        float4 xa = make_float4(0.f, 0.f, 0.f, 0.f);
        if (enc)
            xa = __ldcg((const float4 *)&g_xg[((size_t)st * BB + mo) * NG + bx * 16 + 4 * dl]);

        // ---- GEMM over this warp's k-slice (32 dims)
        float2 acc[4][8];
#pragma unroll
        for (int i = 0; i < 4; ++i)
#pragma unroll
            for (int c = 0; c < 8; ++c) acc[i][c] = make_float2(0.f, 0.f);

        float4 pf[4];
#pragma unroll
        for (int j = 0; j < 4; ++j)
            pf[j] = __ldcg(&hb[(k0 + j) * 32 + lane]);

#pragma unroll 4
        for (int k = 0; k < 32; ++k) {
            float4 hv = pf[k & 3];
            int kn = (k + 4 < 32) ? k + 4 : k;
            pf[k & 3] = __ldcg(&hb[(k0 + kn) * 32 + lane]);
            const float4 *wrow = (const float4 *)&Ws[(k0 + k) * 16];
            const float4 w0 = wrow[0], w1 = wrow[1], w2 = wrow[2], w3 = wrow[3];
            const float av[4] = {hv.x, hv.y, hv.z, hv.w};
#pragma unroll
            for (int i = 0; i < 4; ++i) {
                float2 a = make_float2(av[i], av[i]);
                fma2(acc[i][0], a, make_float2(w0.x, w0.y));
                fma2(acc[i][1], a, make_float2(w0.z, w0.w));
                fma2(acc[i][2], a, make_float2(w1.x, w1.y));
                fma2(acc[i][3], a, make_float2(w1.z, w1.w));
                fma2(acc[i][4], a, make_float2(w2.x, w2.y));
                fma2(acc[i][5], a, make_float2(w2.z, w2.w));
                fma2(acc[i][6], a, make_float2(w3.x, w3.y));
                fma2(acc[i][7], a, make_float2(w3.z, w3.w));
            }
        }

        // ---- store partials (swizzle keeps the reduce read conflict-free)
#pragma unroll
        for (int i = 0; i < 4; ++i) {
            int mp = 4 * lane + i;
            int sw = ((mp >> 1) ^ (mp >> 2)) & 3;
#pragma unroll
            for (int c4 = 0; c4 < 4; ++c4) {
                float4 v = make_float4(acc[i][2 * c4].x,     acc[i][2 * c4].y,
                                       acc[i][2 * c4 + 1].x, acc[i][2 * c4 + 1].y);
                *(float4 *)&part[w * 2048 + mp * 16 + ((c4 ^ sw) * 4)] = v;
            }
        }
        __syncthreads();

        // ---- reduce 16 partials + cell update (one cell per thread)
        {
            int sw = ((mo >> 1) ^ (mo >> 2)) & 3;
            int slot = (dl ^ sw) * 4;
            float4 s = make_float4(0.f, 0.f, 0.f, 0.f);
#pragma unroll
            for (int ww = 0; ww < 16; ++ww) {
                const float4 v = *(const float4 *)&part[ww * 2048 + mo * 16 + slot];
                s.x += v.x; s.y += v.y; s.z += v.z; s.w += v.w;
            }
            float gi = s.x + bias.x + xa.x;
            float gf = s.y + bias.y + xa.y;
            float gg = s.z + bias.z + xa.z;
            float go = s.w + bias.w + xa.w;
            float cn = sigm(gf) * cst + sigm(gi) * tanhf(gg);
            cst = cn;
            float h0 = sigm(go) * tanhf(cn);
            hw[(4 * bx + dl) * BB + mo] = h0;
            if (!enc)
                g_hist[(size_t)(st - SEQ + 1) * BB * DD + (size_t)mo * DD + 4 * bx + dl] = h0;
            else if (st == SEQ - 1)
                g_hist[(size_t)mo * DD + 4 * bx + dl] = h0;
        }
        grid_sync();    // also protects part/Ws reuse next step
    }
}

// ==================== batched output projection ====================
__global__ __launch_bounds__(256) void final_pred(const float *__restrict__ bp,
                                                  float *__restrict__ out)
{
    __shared__ float As[2][8 * 132];
    __shared__ float Bs[2][8 * 128];
    const int t = blockIdx.y, ebase = blockIdx.x * 128, tid = threadIdx.x;
    const int tm8 = (tid >> 4) * 8, tn8 = (tid & 15) * 8;
    const float *A = g_hist + (size_t)t * BB * DD;

    Slots s; make_slots(s, tid);
    float2 acc[8][4];
#pragma unroll
    for (int r = 0; r < 8; ++r)
#pragma unroll
        for (int c = 0; c < 4; ++c) acc[r][c] = make_float2(0.f, 0.f);

    float ar[4], br[4];
    auto load = [&](int kb) {
#pragma unroll
        for (int p = 0; p < 4; ++p) {
            ar[p] = A[(size_t)s.mmp[p] * DD + kb + s.klp[p]];
            br[p] = g_WpT2[(size_t)(kb + s.kwp[p]) * EPAD + ebase + s.nlp[p]];
        }
    };

    int buf = 0;
    load(0);
    stage(s, ar, br, As[0], Bs[0]);
    __syncthreads();
#pragma unroll 1
    for (int c8 = 0; c8 < 64; ++c8) {
        if (c8 < 63) load((c8 + 1) * 8);
        mma8(acc, As[buf], Bs[buf], tm8, tn8);
        if (c8 < 63) { stage(s, ar, br, As[buf ^ 1], Bs[buf ^ 1]); __syncthreads(); buf ^= 1; }
    }
#pragma unroll
    for (int r = 0; r < 8; ++r) {
        int b = tm8 + r;
        float *orow = out + ((size_t)b * PRED + t) * ENC;
        float vals[8] = {acc[r][0].x, acc[r][0].y, acc[r][1].x, acc[r][1].y,
                         acc[r][2].x, acc[r][2].y, acc[r][3].x, acc[r][3].y};
#pragma unroll
        for (int c = 0; c < 8; ++c) {
            int e = ebase + tn8 + c;
            if (e < ENC) orow[e] = vals[c] + bp[e];
        }
    }
}

extern "C" void kernel_launch(void *const *d_in, const int *in_sizes, int n_in,
                              void *d_out, int out_size)
{
    const float *x   = (const float *)d_in[0];
    const float *Wih = (const float *)d_in[1];
    const float *Whh = (const float *)d_in[2];
    const float *bih = (const float *)d_in[3];
    const float *bhh = (const float *)d_in[4];
    const float *Wp  = (const float *)d_in[5];
    const float *bp  = (const float *)d_in[6];
    float *out = (float *)d_out;

    cudaFuncSetAttribute(lstm_persistent,
                         cudaFuncAttributeMaxDynamicSharedMemorySize, LSTM_SMEM);

    prepA<<<4096, 256>>>(Wih, Whh, bih, bhh, Wp);
    prepB<<<NG, 128>>>(Wih, Whh, bp);
    xg_proj<<<dim3(16, SEQ), 256>>>(x);
    lstm_persistent<<<NBLK, 512, LSTM_SMEM>>>();
    final_pred<<<dim3(3, PRED), 256>>>(bp, out);
}

// round 10
// speedup vs baseline: 2.8666x; 1.0773x over previous
#include <cuda_runtime.h>
#include <cstdint>
#include <cstddef>

#define BB   128
#define SEQ  720
#define PRED 336
#define ENC  321
#define DD   512
#define NG   2048           // 4*D
#define XSTR (SEQ*ENC)
#define KXP  328            // ENC padded to 41*8
#define EPAD 384            // ENC padded for W_pred^T tiles
#define NBLK 128            // persistent grid
#define LSTM_SMEM (32768 + 131072)   // Ws strip + 16-warp partials

// -------- persistent device scratch --------
__device__ float g_WX  [KXP * NG];        // Wih^T gate-interleaved [k][n], n=d*4+gate
__device__ float g_WE  [DD * NG];         // Whh^T gate-interleaved
__device__ float g_WD  [DD * NG];         // decoder (Wih@Wp + Whh)^T gate-interleaved
__device__ float g_WpT2[DD * EPAD];       // W_pred^T padded [k][e]
__device__ float g_bias [NG];
__device__ float g_biasd[NG];
__device__ float g_hT[2][DD * BB];        // ping-pong hidden state, TRANSPOSED [dim][m]
__device__ float g_xg[(size_t)SEQ * BB * NG];         // precomputed x projections
__device__ float g_hist[(size_t)PRED * BB * DD];      // decoder h_t log ([t][m][dim])

__device__ volatile unsigned g_flag[NBLK * 32];       // spread flags, 128 B apart

// -------- packed fp32x2 FMA --------
__device__ __forceinline__ void fma2(float2 &d, float2 a, float2 b) {
    unsigned long long &du = reinterpret_cast<unsigned long long &>(d);
    unsigned long long au  = reinterpret_cast<unsigned long long &>(a);
    unsigned long long bu  = reinterpret_cast<unsigned long long &>(b);
    asm("fma.rn.f32x2 %0, %1, %2, %0;" : "+l"(du) : "l"(au), "l"(bu));
}

__device__ __forceinline__ float sigm(float x) { return 1.f / (1.f + __expf(-x)); }

// -------- flag-array grid barrier: arrival = STG, detection = parallel polls --------
__device__ __forceinline__ void grid_sync_flag(unsigned target) {
    __threadfence();                       // every thread's h-stores device-visible
    __syncthreads();
    if (threadIdx.x == 0) g_flag[blockIdx.x * 32] = target;
    if (threadIdx.x < NBLK) {
        while (g_flag[threadIdx.x * 32] < target) { }
    }
    __syncthreads();
}

// -------- GEMM micro-kernel pieces (xg_proj / final_pred) --------
struct Slots { int klp[4], mmp[4], kwp[4], nlp[4]; };

__device__ __forceinline__ void make_slots(Slots &s, int tid) {
#pragma unroll
    for (int p = 0; p < 4; ++p) {
        int lin = tid + p * 256;
        s.klp[p] = lin & 7;   s.mmp[p] = lin >> 3;
        s.nlp[p] = lin & 127; s.kwp[p] = lin >> 7;
    }
}

__device__ __forceinline__ void stage(const Slots &s, const float *ur, const float *wr,
                                      float *U, float *W) {
#pragma unroll
    for (int p = 0; p < 4; ++p) {
        U[s.klp[p] * 132 + s.mmp[p]] = ur[p];
        W[s.kwp[p] * 128 + s.nlp[p]] = wr[p];
    }
}

__device__ __forceinline__ void mma8(float2 acc[8][4], const float *U, const float *W,
                                     int tm8, int tn8) {
#pragma unroll
    for (int q = 0; q < 8; ++q) {
        const float4 a0 = *(const float4 *)&U[q * 132 + tm8];
        const float4 a1 = *(const float4 *)&U[q * 132 + tm8 + 4];
        const float4 b0 = *(const float4 *)&W[q * 128 + tn8];
        const float4 b1 = *(const float4 *)&W[q * 128 + tn8 + 4];
        float  av[8] = {a0.x, a0.y, a0.z, a0.w, a1.x, a1.y, a1.z, a1.w};
        float2 bv[4] = {make_float2(b0.x, b0.y), make_float2(b0.z, b0.w),
                        make_float2(b1.x, b1.y), make_float2(b1.z, b1.w)};
#pragma unroll
        for (int r = 0; r < 8; ++r) {
            float2 ad = make_float2(av[r], av[r]);
#pragma unroll
            for (int c = 0; c < 4; ++c) fma2(acc[r][c], ad, bv[c]);
        }
    }
}

// ==================== prep kernels ====================
__global__ void prepA(const float *__restrict__ Wih, const float *__restrict__ Whh,
                      const float *__restrict__ bih, const float *__restrict__ bhh,
                      const float *__restrict__ Wp)
{
    int idx = blockIdx.x * 256 + threadIdx.x;
    if (idx < KXP * NG) {
        int k = idx / NG, n = idx - k * NG, d = n >> 2, gate = n & 3, j = gate * DD + d;
        g_WX[idx] = (k < ENC) ? Wih[(size_t)j * ENC + k] : 0.f;
    }
    if (idx < DD * NG) {
        int k = idx / NG, n = idx - k * NG, d = n >> 2, gate = n & 3, j = gate * DD + d;
        g_WE[idx] = Whh[(size_t)j * DD + k];
    }
    if (idx < DD * EPAD) {
        int k = idx / EPAD, e = idx - k * EPAD;
        g_WpT2[idx] = (e < ENC) ? Wp[(size_t)e * DD + k] : 0.f;
    }
    if (idx < NG) {
        int j = idx, n = (j & 511) * 4 + (j >> 9);
        g_bias[n] = bih[j] + bhh[j];
    }
    if (idx < 2 * BB * DD) ((float *)g_hT)[idx] = 0.f;
    if (idx < NBLK * 32) g_flag[idx] = 0;   // reset barrier flags every launch (graph replay safe)
}

// g_WD[k][n] = sum_e Wih[j][e]*Wp[e][k] + Whh[j][k];  biasd[n] = bias[n] + Wih[j]·bp
__global__ void prepB(const float *__restrict__ Wih, const float *__restrict__ Whh,
                      const float *__restrict__ bp)
{
    __shared__ float sW[EPAD];
    __shared__ float red[128];
    const int j = blockIdx.x, tid = threadIdx.x;
    for (int e = tid; e < EPAD; e += 128) sW[e] = (e < ENC) ? Wih[(size_t)j * ENC + e] : 0.f;
    __syncthreads();
    const int d = j & 511, gate = j >> 9, n = d * 4 + gate;
    for (int k = tid; k < DD; k += 128) {
        float a0 = 0.f, a1 = 0.f, a2 = 0.f, a3 = 0.f;
        const float *wr = &g_WpT2[(size_t)k * EPAD];
        for (int e = 0; e < EPAD; e += 4) {
            const float4 wv = *(const float4 *)&wr[e];
            const float4 sv = *(const float4 *)&sW[e];
            a0 += sv.x * wv.x; a1 += sv.y * wv.y; a2 += sv.z * wv.z; a3 += sv.w * wv.w;
        }
        g_WD[(size_t)k * NG + n] = (a0 + a1) + (a2 + a3) + Whh[(size_t)j * DD + k];
    }
    float p = 0.f;
    for (int e = tid; e < ENC; e += 128) p += sW[e] * bp[e];
    red[tid] = p; __syncthreads();
    for (int off = 64; off; off >>= 1) { if (tid < off) red[tid] += red[tid + off]; __syncthreads(); }
    if (tid == 0) g_biasd[n] = g_bias[n] + red[0];
}

// ==================== parallel input projection: xg[t][b][n] ====================
__global__ __launch_bounds__(256) void xg_proj(const float *__restrict__ x)
{
    __shared__ float Us[2][8 * 132];
    __shared__ float Ws[2][8 * 128];
    const int t = blockIdx.y, nbase = blockIdx.x * 128, tid = threadIdx.x;
    const int tm8 = (tid >> 4) * 8, tn8 = (tid & 15) * 8;
    const float *xbase = x + (size_t)t * ENC;

    Slots s; make_slots(s, tid);
    float2 acc[8][4];
#pragma unroll
    for (int r = 0; r < 8; ++r)
#pragma unroll
        for (int c = 0; c < 4; ++c) acc[r][c] = make_float2(0.f, 0.f);

    float ur[4], wr[4];
    auto load = [&](int kb) {
#pragma unroll
        for (int p = 0; p < 4; ++p) {
            int k = kb + s.klp[p];
            ur[p] = (k < ENC) ? __ldg(&xbase[(size_t)s.mmp[p] * XSTR + k]) : 0.f;
            wr[p] = g_WX[(size_t)(kb + s.kwp[p]) * NG + nbase + s.nlp[p]];
        }
    };

    int buf = 0;
    load(0);
    stage(s, ur, wr, Us[0], Ws[0]);
    __syncthreads();
#pragma unroll 1
    for (int c8 = 0; c8 < 41; ++c8) {
        if (c8 < 40) load((c8 + 1) * 8);
        mma8(acc, Us[buf], Ws[buf], tm8, tn8);
        if (c8 < 40) { stage(s, ur, wr, Us[buf ^ 1], Ws[buf ^ 1]); __syncthreads(); buf ^= 1; }
    }
#pragma unroll
    for (int r = 0; r < 8; ++r) {
        float *dst = &g_xg[((size_t)t * BB + tm8 + r) * NG + nbase + tn8];
        *(float4 *)dst       = make_float4(acc[r][0].x, acc[r][0].y, acc[r][1].x, acc[r][1].y);
        *(float4 *)(dst + 4) = make_float4(acc[r][2].x, acc[r][2].y, acc[r][3].x, acc[r][3].y);
    }
}

// ==================== persistent recurrent kernel ====================
// 128 blocks x 512 threads (16 warps, 4/SMSP). Block bx owns gate-cols
// [16bx,16bx+16) == dims [4bx,4bx+4). Warp w owns k-slice [32w,32w+32);
// lane L covers batches 4L..4L+4 (float4 straight from transposed h in L2).
// Partials (16 x 128 x 16 floats, 128 KB smem) reduced once: each thread owns
// ONE cell (m = tid&127, dl = tid>>7) with c resident in a register.
// One flag-array grid barrier per step; no other global sync.
__global__ __launch_bounds__(512, 1) void lstm_persistent()
{
    extern __shared__ float dsm[];
    float *Ws   = dsm;                  // [512][16]  weight strip, 32 KB
    float *part = dsm + DD * 16;        // [16][128][16] partials, 128 KB

    const int tid = threadIdx.x, bx = blockIdx.x;
    const int w = tid >> 5, lane = tid & 31;
    const int k0 = 32 * w;
    const int dl = tid >> 7;            // 0..3  (cell dim within block)
    const int mo = tid & 127;           // cell batch

    // step-invariant addressing (hoisted out of the 1055-step loop)
    float *stp[4];                      // partial-store pointers per i
    int    ssw[4];                      // per-i swizzle
#pragma unroll
    for (int i = 0; i < 4; ++i) {
        int mp = 4 * lane + i;
        ssw[i] = ((mp >> 1) ^ (mp >> 2)) & 3;
        stp[i] = &part[w * 2048 + mp * 16];
    }
    const int rslot = (dl ^ (((mo >> 1) ^ (mo >> 2)) & 3)) * 4;
    const float *rptr = &part[mo * 16 + rslot];
    const int laneoff = k0 * 32 + lane;

    for (int i = tid; i < DD * 16; i += 512)
        Ws[i] = g_WE[(size_t)(i >> 4) * NG + bx * 16 + (i & 15)];
    float4 bias = *(const float4 *)&g_bias[bx * 16 + 4 * dl];
    float cst = 0.f;
    __syncthreads();

    for (int st = 0; st < SEQ + PRED - 1; ++st) {
        const bool enc = (st < SEQ);
        if (st == SEQ) {                 // switch to decoder weights
            for (int i = tid; i < DD * 16; i += 512)
                Ws[i] = g_WD[(size_t)(i >> 4) * NG + bx * 16 + (i & 15)];
            bias = *(const float4 *)&g_biasd[bx * 16 + 4 * dl];
            __syncthreads();
        }
        const float4 *hb = (const float4 *)g_hT[st & 1] + laneoff;
        float *hw = g_hT[(st & 1) ^ 1];

        // prefetch xg for this thread's cell — consumed after the GEMM
        float4 xa = make_float4(0.f, 0.f, 0.f, 0.f);
        if (enc)
            xa = __ldcg((const float4 *)&g_xg[((size_t)st * BB + mo) * NG + bx * 16 + 4 * dl]);

        // ---- GEMM over this warp's k-slice (32 dims)
        float2 acc[4][8];
#pragma unroll
        for (int i = 0; i < 4; ++i)
#pragma unroll
            for (int c = 0; c < 8; ++c) acc[i][c] = make_float2(0.f, 0.f);

        float4 pf[4];
#pragma unroll
        for (int j = 0; j < 4; ++j)
            pf[j] = __ldcg(hb + j * 32);

        const float4 *wp = (const float4 *)&Ws[k0 * 16];
#pragma unroll 4
        for (int k = 0; k < 32; ++k) {
            float4 hv = pf[k & 3];
            pf[k & 3] = __ldcg(hb + ((k + 4) & 31) * 32);  // wrap: tail reloads, harmless
            const float4 w0 = wp[k * 4 + 0], w1 = wp[k * 4 + 1];
            const float4 w2 = wp[k * 4 + 2], w3 = wp[k * 4 + 3];
            const float av[4] = {hv.x, hv.y, hv.z, hv.w};
#pragma unroll
            for (int i = 0; i < 4; ++i) {
                float2 a = make_float2(av[i], av[i]);
                fma2(acc[i][0], a, make_float2(w0.x, w0.y));
                fma2(acc[i][1], a, make_float2(w0.z, w0.w));
                fma2(acc[i][2], a, make_float2(w1.x, w1.y));
                fma2(acc[i][3], a, make_float2(w1.z, w1.w));
                fma2(acc[i][4], a, make_float2(w2.x, w2.y));
                fma2(acc[i][5], a, make_float2(w2.z, w2.w));
                fma2(acc[i][6], a, make_float2(w3.x, w3.y));
                fma2(acc[i][7], a, make_float2(w3.z, w3.w));
            }
        }

        // ---- store partials (swizzled so the reduce read is conflict-free)
#pragma unroll
        for (int i = 0; i < 4; ++i) {
#pragma unroll
            for (int c4 = 0; c4 < 4; ++c4) {
                float4 v = make_float4(acc[i][2 * c4].x,     acc[i][2 * c4].y,
                                       acc[i][2 * c4 + 1].x, acc[i][2 * c4 + 1].y);
                *(float4 *)(stp[i] + ((c4 ^ ssw[i]) * 4)) = v;
            }
        }
        __syncthreads();

        // ---- reduce 16 partials + cell update (one cell per thread)
        {
            float4 s = make_float4(0.f, 0.f, 0.f, 0.f);
#pragma unroll
            for (int ww = 0; ww < 16; ++ww) {
                const float4 v = *(const float4 *)(rptr + ww * 2048);
                s.x += v.x; s.y += v.y; s.z += v.z; s.w += v.w;
            }
            float gi = s.x + bias.x + xa.x;
            float gf = s.y + bias.y + xa.y;
            float gg = s.z + bias.z + xa.z;
            float go = s.w + bias.w + xa.w;
            float cn = sigm(gf) * cst + sigm(gi) * tanhf(gg);
            cst = cn;
            float h0 = sigm(go) * tanhf(cn);
            hw[(4 * bx + dl) * BB + mo] = h0;
            if (!enc)
                g_hist[(size_t)(st - SEQ + 1) * BB * DD + (size_t)mo * DD + 4 * bx + dl] = h0;
            else if (st == SEQ - 1)
                g_hist[(size_t)mo * DD + 4 * bx + dl] = h0;
        }
        grid_sync_flag((unsigned)(st + 1));    // also fences part/Ws reuse next step
    }
}

// ==================== batched output projection ====================
__global__ __launch_bounds__(256) void final_pred(const float *__restrict__ bp,
                                                  float *__restrict__ out)
{
    __shared__ float As[2][8 * 132];
    __shared__ float Bs[2][8 * 128];
    const int t = blockIdx.y, ebase = blockIdx.x * 128, tid = threadIdx.x;
    const int tm8 = (tid >> 4) * 8, tn8 = (tid & 15) * 8;
    const float *A = g_hist + (size_t)t * BB * DD;

    Slots s; make_slots(s, tid);
    float2 acc[8][4];
#pragma unroll
    for (int r = 0; r < 8; ++r)
#pragma unroll
        for (int c = 0; c < 4; ++c) acc[r][c] = make_float2(0.f, 0.f);

    float ar[4], br[4];
    auto load = [&](int kb) {
#pragma unroll
        for (int p = 0; p < 4; ++p) {
            ar[p] = A[(size_t)s.mmp[p] * DD + kb + s.klp[p]];
            br[p] = g_WpT2[(size_t)(kb + s.kwp[p]) * EPAD + ebase + s.nlp[p]];
        }
    };

    int buf = 0;
    load(0);
    stage(s, ar, br, As[0], Bs[0]);
    __syncthreads();
#pragma unroll 1
    for (int c8 = 0; c8 < 64; ++c8) {
        if (c8 < 63) load((c8 + 1) * 8);
        mma8(acc, As[buf], Bs[buf], tm8, tn8);
        if (c8 < 63) { stage(s, ar, br, As[buf ^ 1], Bs[buf ^ 1]); __syncthreads(); buf ^= 1; }
    }
#pragma unroll
    for (int r = 0; r < 8; ++r) {
        int b = tm8 + r;
        float *orow = out + ((size_t)b * PRED + t) * ENC;
        float vals[8] = {acc[r][0].x, acc[r][0].y, acc[r][1].x, acc[r][1].y,
                         acc[r][2].x, acc[r][2].y, acc[r][3].x, acc[r][3].y};
#pragma unroll
        for (int c = 0; c < 8; ++c) {
            int e = ebase + tn8 + c;
            if (e < ENC) orow[e] = vals[c] + bp[e];
        }
    }
}

extern "C" void kernel_launch(void *const *d_in, const int *in_sizes, int n_in,
                              void *d_out, int out_size)
{
    const float *x   = (const float *)d_in[0];
    const float *Wih = (const float *)d_in[1];
    const float *Whh = (const float *)d_in[2];
    const float *bih = (const float *)d_in[3];
    const float *bhh = (const float *)d_in[4];
    const float *Wp  = (const float *)d_in[5];
    const float *bp  = (const float *)d_in[6];
    float *out = (float *)d_out;

    cudaFuncSetAttribute(lstm_persistent,
                         cudaFuncAttributeMaxDynamicSharedMemorySize, LSTM_SMEM);

    prepA<<<4096, 256>>>(Wih, Whh, bih, bhh, Wp);
    prepB<<<NG, 128>>>(Wih, Whh, bp);
    xg_proj<<<dim3(16, SEQ), 256>>>(x);
    lstm_persistent<<<NBLK, 512, LSTM_SMEM>>>();
    final_pred<<<dim3(3, PRED), 256>>>(bp, out);
}